// round 2
// baseline (speedup 1.0000x reference)
#include <cuda_runtime.h>
#include <cstdint>

// ---------------- problem constants ----------------
#define S_FRAMES 128
#define HW       50176          // 224*224
#define NPTS     (S_FRAMES*HW)  // 6,422,528
#define GDIM     48
#define VVOX     (GDIM*GDIM*GDIM)   // 110592
#define VW       (VVOX/32)          // 3456 words
#define K_SEL    16
#define RANK_LO  25087          // floor(0.5*(HW-1))
#define CONF_THR 0.1f

// ---------------- device scratch (no allocations allowed) ----------------
__device__ float    g_pct[S_FRAMES];
__device__ float    g_pmin[3];
__device__ float    g_pmax[3];
__device__ float    g_voxsize;
__device__ unsigned g_occ[S_FRAMES][VW];   // 1.77 MB
__device__ unsigned g_covered[VW];
__device__ int      g_gains[S_FRAMES];
__device__ int      g_selflag[S_FRAMES];
__device__ int      g_sel[K_SEL];
__device__ float    g_scores[K_SEL];

// ---------------- helpers ----------------
__device__ __forceinline__ void atomicMinF(float* addr, float v) {
    unsigned* ua = (unsigned*)addr;
    unsigned old = *ua;
    while (__uint_as_float(old) > v) {
        unsigned assumed = old;
        old = atomicCAS(ua, assumed, __float_as_uint(v));
        if (old == assumed) break;
    }
}
__device__ __forceinline__ void atomicMaxF(float* addr, float v) {
    unsigned* ua = (unsigned*)addr;
    unsigned old = *ua;
    while (__uint_as_float(old) < v) {
        unsigned assumed = old;
        old = atomicCAS(ua, assumed, __float_as_uint(v));
        if (old == assumed) break;
    }
}

// ---------------- init: zero scratch + output ----------------
__global__ void k_init(float* out, int out_size) {
    int i = blockIdx.x * blockDim.x + threadIdx.x;
    int stride = gridDim.x * blockDim.x;
    unsigned* occ_flat = (unsigned*)g_occ;
    for (int w = i; w < S_FRAMES * VW; w += stride) occ_flat[w] = 0u;
    for (int w = i; w < VW; w += stride) g_covered[w] = 0u;
    if (i < S_FRAMES) g_selflag[i] = 0;
    if (i < 3) { g_pmin[i] = 1e30f; g_pmax[i] = -1e30f; }
    for (int w = i; w < out_size; w += stride) out[w] = 0.0f;
}

// ---------------- per-frame exact percentile via radix select ----------------
// conf values are in [0,1): positive floats => u32 bit pattern is order-isomorphic.
__global__ void k_percentile(const float* __restrict__ conf) {
    __shared__ unsigned hist[256];
    __shared__ unsigned s_prefix;
    __shared__ int      s_rank;
    __shared__ unsigned s_val[2];

    const float* c = conf + (size_t)blockIdx.x * HW;

    for (int sel = 0; sel < 2; sel++) {
        unsigned prefix = 0u, pmask = 0u;
        if (threadIdx.x == 0) s_rank = RANK_LO + sel;
        __syncthreads();
        for (int pass = 0; pass < 4; pass++) {
            int shift = 24 - 8 * pass;
            for (int b = threadIdx.x; b < 256; b += blockDim.x) hist[b] = 0u;
            __syncthreads();
            for (int j = threadIdx.x; j < HW; j += blockDim.x) {
                unsigned u = __float_as_uint(c[j]);
                if ((u & pmask) == prefix) atomicAdd(&hist[(u >> shift) & 255u], 1u);
            }
            __syncthreads();
            if (threadIdx.x == 0) {
                int r = s_rank;
                unsigned cum = 0u;
                int b = 0;
                for (; b < 256; b++) {
                    if (cum + hist[b] > (unsigned)r) break;
                    cum += hist[b];
                }
                s_rank = r - (int)cum;
                s_prefix = prefix | ((unsigned)b << shift);
            }
            __syncthreads();
            prefix = s_prefix;
            pmask |= (255u << shift);
            __syncthreads();
        }
        if (threadIdx.x == 0) s_val[sel] = prefix;
        __syncthreads();
    }
    if (threadIdx.x == 0) {
        float vl = __uint_as_float(s_val[0]);
        float vh = __uint_as_float(s_val[1]);
        // jnp.quantile linear interp with frac=0.5: vl*0.5 + vh*0.5
        g_pct[blockIdx.x] = 0.5f * vl + 0.5f * vh;
    }
}

// ---------------- global min/max of valid points ----------------
__global__ void k_minmax(const float* __restrict__ wp, const float* __restrict__ conf) {
    int i0 = blockIdx.x * blockDim.x + threadIdx.x;
    int stride = gridDim.x * blockDim.x;
    float mn[3] = {1e30f, 1e30f, 1e30f};
    float mx[3] = {-1e30f, -1e30f, -1e30f};
    for (int i = i0; i < NPTS; i += stride) {
        float cv = conf[i];
        int f = i / HW;
        if (cv > CONF_THR && cv >= g_pct[f]) {
            const float* p = wp + (size_t)i * 3;
            #pragma unroll
            for (int d = 0; d < 3; d++) {
                float v = p[d];
                mn[d] = fminf(mn[d], v);
                mx[d] = fmaxf(mx[d], v);
            }
        }
    }
    // warp reduce
    #pragma unroll
    for (int off = 16; off; off >>= 1) {
        #pragma unroll
        for (int d = 0; d < 3; d++) {
            mn[d] = fminf(mn[d], __shfl_down_sync(0xFFFFFFFFu, mn[d], off));
            mx[d] = fmaxf(mx[d], __shfl_down_sync(0xFFFFFFFFu, mx[d], off));
        }
    }
    __shared__ float smn[3][8], smx[3][8];
    int wid = threadIdx.x >> 5, lid = threadIdx.x & 31;
    if (lid == 0) {
        #pragma unroll
        for (int d = 0; d < 3; d++) { smn[d][wid] = mn[d]; smx[d][wid] = mx[d]; }
    }
    __syncthreads();
    if (threadIdx.x == 0) {
        int nw = (blockDim.x + 31) >> 5;
        #pragma unroll
        for (int d = 0; d < 3; d++) {
            float a = 1e30f, b = -1e30f;
            for (int w = 0; w < nw; w++) { a = fminf(a, smn[d][w]); b = fmaxf(b, smx[d][w]); }
            if (a < 1e30f)  atomicMinF(&g_pmin[d], a);
            if (b > -1e30f) atomicMaxF(&g_pmax[d], b);
        }
    }
}

// ---------------- voxel size ----------------
__global__ void k_vsize() {
    float e0 = g_pmax[0] - g_pmin[0];
    float e1 = g_pmax[1] - g_pmin[1];
    float e2 = g_pmax[2] - g_pmin[2];
    g_voxsize = __fdiv_rn(fminf(fminf(e0, e1), e2), 20.0f);
}

// ---------------- build occupancy bitmaps ----------------
__global__ void k_occ(const float* __restrict__ wp, const float* __restrict__ conf) {
    int i0 = blockIdx.x * blockDim.x + threadIdx.x;
    int stride = gridDim.x * blockDim.x;
    float vs = g_voxsize;
    float p0 = g_pmin[0], p1 = g_pmin[1], p2 = g_pmin[2];
    for (int i = i0; i < NPTS; i += stride) {
        float cv = conf[i];
        int f = i / HW;
        if (cv > CONF_THR && cv >= g_pct[f]) {
            const float* p = wp + (size_t)i * 3;
            int ix = (int)floorf(__fdiv_rn(p[0] - p0, vs));
            int iy = (int)floorf(__fdiv_rn(p[1] - p1, vs));
            int iz = (int)floorf(__fdiv_rn(p[2] - p2, vs));
            ix = min(max(ix, 0), GDIM - 1);
            iy = min(max(iy, 0), GDIM - 1);
            iz = min(max(iz, 0), GDIM - 1);
            int vid = (ix * GDIM + iy) * GDIM + iz;
            atomicOr(&g_occ[f][vid >> 5], 1u << (vid & 31));
        }
    }
}

// ---------------- greedy: per-frame gains ----------------
__global__ void k_gain() {
    int s = blockIdx.x;
    int acc = 0;
    const unsigned* row = g_occ[s];
    for (int w = threadIdx.x; w < VW; w += blockDim.x)
        acc += __popc(row[w] & ~g_covered[w]);
    #pragma unroll
    for (int off = 16; off; off >>= 1)
        acc += __shfl_down_sync(0xFFFFFFFFu, acc, off);
    __shared__ int sred[8];
    int wid = threadIdx.x >> 5, lid = threadIdx.x & 31;
    if (lid == 0) sred[wid] = acc;
    __syncthreads();
    if (threadIdx.x == 0) {
        int tot = 0;
        int nw = (blockDim.x + 31) >> 5;
        for (int w = 0; w < nw; w++) tot += sred[w];
        g_gains[s] = tot;
    }
}

// ---------------- greedy: argmax (first-max) + covered update ----------------
__global__ void k_select(int it) {
    __shared__ int s_best;
    if (threadIdx.x == 0) {
        int bg = -2, bs = 0;
        for (int s = 0; s < S_FRAMES; s++) {
            int g = g_selflag[s] ? -1 : g_gains[s];
            if (g > bg) { bg = g; bs = s; }   // strict > == first max (jnp.argmax tie-break)
        }
        g_selflag[bs] = 1;
        g_sel[it] = bs;
        g_scores[it] = (float)bg;
        s_best = bs;
    }
    __syncthreads();
    int bs = s_best;
    const unsigned* row = g_occ[bs];
    for (int w = threadIdx.x; w < VW; w += blockDim.x)
        g_covered[w] |= row[w];
}

// ---------------- finalize: write [sel(16), scores(16), total(1)] as f32 ----------------
__global__ void k_final(float* out, int out_size) {
    int acc = 0;
    for (int w = threadIdx.x; w < VW; w += blockDim.x)
        acc += __popc(g_covered[w]);
    #pragma unroll
    for (int off = 16; off; off >>= 1)
        acc += __shfl_down_sync(0xFFFFFFFFu, acc, off);
    __shared__ int sred[8];
    int wid = threadIdx.x >> 5, lid = threadIdx.x & 31;
    if (lid == 0) sred[wid] = acc;
    __syncthreads();

    int t = threadIdx.x;
    if (t < K_SEL && t < out_size) out[t] = (float)g_sel[t];
    if (t >= K_SEL && t < 2 * K_SEL && t < out_size) out[t] = g_scores[t - K_SEL];
    if (t == 0) {
        int total = 0;
        int nw = (blockDim.x + 31) >> 5;
        for (int w = 0; w < nw; w++) total += sred[w];
        if (2 * K_SEL < out_size) out[2 * K_SEL] = (float)total;
    }
}

// ---------------- launch ----------------
extern "C" void kernel_launch(void* const* d_in, const int* in_sizes, int n_in,
                              void* d_out, int out_size) {
    // metadata order: depth, depth_conf, world_points, world_points_conf, pose_enc
    const float* wp   = (const float*)d_in[2];
    const float* conf = (const float*)d_in[3];
    float* out = (float*)d_out;

    k_init<<<512, 256>>>(out, out_size);
    k_percentile<<<S_FRAMES, 512>>>(conf);
    k_minmax<<<2048, 256>>>(wp, conf);
    k_vsize<<<1, 1>>>();
    k_occ<<<2048, 256>>>(wp, conf);
    for (int it = 0; it < K_SEL; it++) {
        k_gain<<<S_FRAMES, 256>>>();
        k_select<<<1, 128>>>(it);
    }
    k_final<<<1, 256>>>(out, out_size);
}